// round 1
// baseline (speedup 1.0000x reference)
#include <cuda_runtime.h>

#define POOL   7
#define NPIX   49
#define BATCH  2
#define NBOX   1000
#define CCH    256
#define C4     (CCH / 4)

// Output slot for each input box (stable sort by level). Device scratch
// (no cudaMalloc allowed).
__device__ int g_slot[BATCH * NBOX];

// ---------------------------------------------------------------------------
// Kernel 1: stable-argsort slot computation.
// slot(i) = #{j : level[j] < level[i]} + #{j < i : level[j] == level[i]}
// One block per batch, levels cached in shared memory, O(N^2) scan spread
// across the block (N=1000 -> ~1000 shared loads per thread, broadcast).
// ---------------------------------------------------------------------------
__global__ void slot_kernel(const int* __restrict__ level) {
    __shared__ int sh[NBOX];
    const int b = blockIdx.x;
    const int* lv = level + b * NBOX;
    for (int i = threadIdx.x; i < NBOX; i += blockDim.x) sh[i] = lv[i];
    __syncthreads();
    for (int i = threadIdx.x; i < NBOX; i += blockDim.x) {
        const int li = sh[i];
        int cnt = 0;
        #pragma unroll 4
        for (int j = 0; j < NBOX; ++j) {
            const int lj = sh[j];
            cnt += (lj < li) || (lj == li && j < i);
        }
        g_slot[b * NBOX + i] = cnt;
    }
}

// ---------------------------------------------------------------------------
// Kernel 2: bilinear crop-and-resize, float4-vectorized over channels.
// One thread per (box, pooled pixel, 4-channel group).
// ---------------------------------------------------------------------------
__global__ __launch_bounds__(256) void roi_kernel(
    const float* __restrict__ boxes,
    const float* __restrict__ fm0,
    const float* __restrict__ fm1,
    const float* __restrict__ fm2,
    const float* __restrict__ fm3,
    const int*   __restrict__ level,
    float*       __restrict__ out)
{
    const int total = BATCH * NBOX * NPIX * C4;
    const int idx = blockIdx.x * blockDim.x + threadIdx.x;
    if (idx >= total) return;

    const int c4  = idx % C4;
    const int t   = idx / C4;
    const int pix = t % NPIX;
    const int box = t / NPIX;          // flat box index in [0, BATCH*NBOX)
    const int b   = box / NBOX;
    const int py  = pix / POOL;
    const int px  = pix % POOL;

    // Select feature map by level (1..4)
    const int lv = __ldg(level + box) - 1;
    const float* fm;
    int S;
    switch (lv) {
        case 0:  fm = fm0; S = 256; break;
        case 1:  fm = fm1; S = 128; break;
        case 2:  fm = fm2; S = 64;  break;
        default: fm = fm3; S = 32;  break;
    }
    const float sm1 = (float)(S - 1);

    const float y1 = __ldg(boxes + box * 4 + 0);
    const float x1 = __ldg(boxes + box * 4 + 1);
    const float y2 = __ldg(boxes + box * 4 + 2);
    const float x2 = __ldg(boxes + box * 4 + 3);

    const float step_y = (y2 - y1) * sm1 * (1.0f / (POOL - 1));
    const float step_x = (x2 - x1) * sm1 * (1.0f / (POOL - 1));
    const float in_y = y1 * sm1 + (float)py * step_y;
    const float in_x = x1 * sm1 + (float)px * step_x;

    const bool valid = (in_y >= 0.0f) && (in_y <= sm1) &&
                       (in_x >= 0.0f) && (in_x <= sm1);

    const float fy = floorf(in_y);
    const float fx = floorf(in_x);
    const int ty = (int)fminf(fmaxf(fy, 0.0f), sm1);
    const int by = min(ty + 1, S - 1);
    const int lx = (int)fminf(fmaxf(fx, 0.0f), sm1);
    const int rx = min(lx + 1, S - 1);
    const float wy = in_y - fy;
    const float wx = in_x - fx;

    const size_t rowT = (size_t)(b * S + ty) * (size_t)S;
    const size_t rowB = (size_t)(b * S + by) * (size_t)S;
    const float4* f4 = (const float4*)fm;

    const float4 tl = __ldg(f4 + (rowT + (size_t)lx) * C4 + c4);
    const float4 tr = __ldg(f4 + (rowT + (size_t)rx) * C4 + c4);
    const float4 bl = __ldg(f4 + (rowB + (size_t)lx) * C4 + c4);
    const float4 br = __ldg(f4 + (rowB + (size_t)rx) * C4 + c4);

    float4 r;
    {
        float top, bot;
        top = tl.x + (tr.x - tl.x) * wx; bot = bl.x + (br.x - bl.x) * wx;
        r.x = top + (bot - top) * wy;
        top = tl.y + (tr.y - tl.y) * wx; bot = bl.y + (br.y - bl.y) * wx;
        r.y = top + (bot - top) * wy;
        top = tl.z + (tr.z - tl.z) * wx; bot = bl.z + (br.z - bl.z) * wx;
        r.z = top + (bot - top) * wy;
        top = tl.w + (tr.w - tl.w) * wx; bot = bl.w + (br.w - bl.w) * wx;
        r.w = top + (bot - top) * wy;
    }
    if (!valid) r = make_float4(0.0f, 0.0f, 0.0f, 0.0f);

    const int slot = g_slot[box];
    float4* o4 = (float4*)out;
    o4[(((size_t)b * NBOX + (size_t)slot) * NPIX + (size_t)pix) * C4 + c4] = r;
}

// ---------------------------------------------------------------------------
// Launch
// ---------------------------------------------------------------------------
extern "C" void kernel_launch(void* const* d_in, const int* in_sizes, int n_in,
                              void* d_out, int out_size) {
    const float* boxes = (const float*)d_in[0];
    const float* fm0   = (const float*)d_in[1];
    const float* fm1   = (const float*)d_in[2];
    const float* fm2   = (const float*)d_in[3];
    const float* fm3   = (const float*)d_in[4];
    const int*   level = (const int*)  d_in[5];
    float*       out   = (float*)d_out;

    slot_kernel<<<BATCH, 1024>>>(level);

    const int total = BATCH * NBOX * NPIX * C4;   // 6,272,000 threads
    const int threads = 256;
    const int blocks = (total + threads - 1) / threads;
    roi_kernel<<<blocks, threads>>>(boxes, fm0, fm1, fm2, fm3, level, out);
}

// round 2
// speedup vs baseline: 2.0520x; 2.0520x over previous
#include <cuda_runtime.h>

#define POOL   7
#define NPIX   49
#define BATCH  2
#define NBOX   1000
#define CCH    256
#define C4     (CCH / 4)
#define ITEMS  (NPIX * C4)      // 3136 per box

__device__ int g_slot[BATCH * NBOX];

// ---------------------------------------------------------------------------
// Kernel 1: stable argsort slot via 4-way counting-sort prefix scan.
// One block per batch (1024 threads >= NBOX). Packed counters:
//   warp phase: 4 x 8-bit fields in a uint32 (per-warp counts <= 32)
//   block phase: 4 x 16-bit fields in a uint64 (totals <= 1000)
// slot(i) = (#boxes with lower level) + (#earlier boxes with equal level)
// ---------------------------------------------------------------------------
__global__ void slot_kernel(const int* __restrict__ level) {
    const int b = blockIdx.x, tid = threadIdx.x;
    const int warp = tid >> 5, lane = tid & 31;
    __shared__ unsigned long long warpBase[32];
    __shared__ unsigned long long levelBase;
    __shared__ unsigned long long warpTot[32];

    const int lv = (tid < NBOX) ? level[b * NBOX + tid] : 0;   // 1..4 (0 = pad)
    const unsigned p = (lv >= 1) ? (1u << (8 * (lv - 1))) : 0u;

    unsigned incl = p;
    #pragma unroll
    for (int d = 1; d < 32; d <<= 1) {
        unsigned n = __shfl_up_sync(0xffffffffu, incl, d);
        if (lane >= d) incl += n;
    }
    if (lane == 31) {
        unsigned long long t = 0;
        t |= (unsigned long long)( incl        & 0xFF);
        t |= (unsigned long long)((incl >>  8) & 0xFF) << 16;
        t |= (unsigned long long)((incl >> 16) & 0xFF) << 32;
        t |= (unsigned long long)((incl >> 24) & 0xFF) << 48;
        warpTot[warp] = t;
    }
    __syncthreads();
    if (tid == 0) {
        unsigned long long run = 0;
        #pragma unroll
        for (int w = 0; w < 32; ++w) { warpBase[w] = run; run += warpTot[w]; }
        const unsigned t1 =  run        & 0xFFFF;
        const unsigned t2 = (run >> 16) & 0xFFFF;
        const unsigned t3 = (run >> 32) & 0xFFFF;
        unsigned long long lb = 0;
        lb |= (unsigned long long)(t1)           << 16;
        lb |= (unsigned long long)(t1 + t2)      << 32;
        lb |= (unsigned long long)(t1 + t2 + t3) << 48;
        levelBase = lb;
    }
    __syncthreads();
    if (tid < NBOX) {
        const int f = lv - 1;
        const unsigned myExcl = ((incl - p) >> (8 * f)) & 0xFF;
        const unsigned wb   = (unsigned)((warpBase[warp] >> (16 * f)) & 0xFFFF);
        const unsigned base = (unsigned)((levelBase      >> (16 * f)) & 0xFFFF);
        g_slot[b * NBOX + tid] = (int)(base + wb + myExcl);
    }
}

// ---------------------------------------------------------------------------
// Kernel 2: one block per box. 49 threads precompute pixel params into
// shared; all 512 threads then stream 49x64 float4 items (2 broadcast
// LDS.128 + 4 LDG.128 + lerp + 1 STG.128 each). Output is contiguous
// per block (slot-permuted base).
// ---------------------------------------------------------------------------
__global__ __launch_bounds__(512) void roi_kernel(
    const float* __restrict__ boxes,
    const float* __restrict__ fm0,
    const float* __restrict__ fm1,
    const float* __restrict__ fm2,
    const float* __restrict__ fm3,
    const int*   __restrict__ level,
    float*       __restrict__ out)
{
    __shared__ int4   sIdx[NPIX];   // corner base indices (float4 units)
    __shared__ float4 sW[NPIX];     // {wy, wx, validf, -}

    const int box = blockIdx.x;              // 0..1999
    const int b   = (box >= NBOX) ? 1 : 0;
    const int tid = threadIdx.x;

    const int lv = __ldg(level + box) - 1;   // 0..3
    const float* fm; int S;
    switch (lv) {
        case 0:  fm = fm0; S = 256; break;
        case 1:  fm = fm1; S = 128; break;
        case 2:  fm = fm2; S = 64;  break;
        default: fm = fm3; S = 32;  break;
    }

    if (tid < NPIX) {
        const int py = tid / POOL;
        const int px = tid - py * POOL;
        const float sm1 = (float)(S - 1);

        const float y1 = __ldg(boxes + box * 4 + 0);
        const float x1 = __ldg(boxes + box * 4 + 1);
        const float y2 = __ldg(boxes + box * 4 + 2);
        const float x2 = __ldg(boxes + box * 4 + 3);

        // Match reference arithmetic exactly (incl. division by pool-1)
        const float in_y = y1 * sm1 + (float)py * ((y2 - y1) * sm1 / 6.0f);
        const float in_x = x1 * sm1 + (float)px * ((x2 - x1) * sm1 / 6.0f);

        const bool valid = (in_y >= 0.0f) && (in_y <= sm1) &&
                           (in_x >= 0.0f) && (in_x <= sm1);

        const float fy = floorf(in_y);
        const float fx = floorf(in_x);
        const int ty = (int)fminf(fmaxf(fy, 0.0f), sm1);
        const int by = min(ty + 1, S - 1);
        const int lx = (int)fminf(fmaxf(fx, 0.0f), sm1);
        const int rx = min(lx + 1, S - 1);

        const int rowT = (b * S + ty) * S;
        const int rowB = (b * S + by) * S;
        sIdx[tid] = make_int4((rowT + lx) * C4, (rowT + rx) * C4,
                              (rowB + lx) * C4, (rowB + rx) * C4);
        sW[tid] = make_float4(in_y - fy, in_x - fx, valid ? 1.0f : 0.0f, 0.0f);
    }
    __syncthreads();

    const float4* f4 = (const float4*)fm;
    const int slot = g_slot[box];
    float4* o4 = (float4*)out + (size_t)(b * NBOX + slot) * ITEMS;

    #pragma unroll
    for (int i = tid; i < ITEMS; i += 512) {
        const int pix = i >> 6;        // / C4
        const int c4  = i & (C4 - 1);
        const int4   id = sIdx[pix];
        const float4 w  = sW[pix];     // w.x=wy, w.y=wx, w.z=valid

        const float4 tl = __ldg(f4 + id.x + c4);
        const float4 tr = __ldg(f4 + id.y + c4);
        const float4 bl = __ldg(f4 + id.z + c4);
        const float4 br = __ldg(f4 + id.w + c4);

        float4 r;
        {
            float top, bot;
            top = tl.x + (tr.x - tl.x) * w.y; bot = bl.x + (br.x - bl.x) * w.y;
            r.x = (top + (bot - top) * w.x) * w.z;
            top = tl.y + (tr.y - tl.y) * w.y; bot = bl.y + (br.y - bl.y) * w.y;
            r.y = (top + (bot - top) * w.x) * w.z;
            top = tl.z + (tr.z - tl.z) * w.y; bot = bl.z + (br.z - bl.z) * w.y;
            r.z = (top + (bot - top) * w.x) * w.z;
            top = tl.w + (tr.w - tl.w) * w.y; bot = bl.w + (br.w - bl.w) * w.y;
            r.w = (top + (bot - top) * w.x) * w.z;
        }
        o4[i] = r;
    }
}

// ---------------------------------------------------------------------------
// Launch
// ---------------------------------------------------------------------------
extern "C" void kernel_launch(void* const* d_in, const int* in_sizes, int n_in,
                              void* d_out, int out_size) {
    const float* boxes = (const float*)d_in[0];
    const float* fm0   = (const float*)d_in[1];
    const float* fm1   = (const float*)d_in[2];
    const float* fm2   = (const float*)d_in[3];
    const float* fm3   = (const float*)d_in[4];
    const int*   level = (const int*)  d_in[5];
    float*       out   = (float*)d_out;

    slot_kernel<<<BATCH, 1024>>>(level);
    roi_kernel<<<BATCH * NBOX, 512>>>(boxes, fm0, fm1, fm2, fm3, level, out);
}